// round 10
// baseline (speedup 1.0000x reference)
#include <cuda_runtime.h>
#include <math.h>

// ---------------------------------------------------------------------------
// ROPE_64252710748794: out = 2 * 1.57 * sum_k sin(C(theta_k)) * vec[2k]
// (theta pairs bitwise equal => pair collapse; see earlier rounds).
// est entirely in registers (round 6: smem in est chain collapses MLP).
// Round 10: DRAM% pinned ~65% across occ/instruction changes => per-warp MLP
// is the binder. Widen to 4 outstanding LDG.128 (2 KB) per warp: each thread
// streams two float4 columns (i, i+stride) per iteration, double-buffered,
// exact 16-iteration division, unconditional steady-state loads.
// ---------------------------------------------------------------------------

#define TWO_PI_F   6.283185307179586f
#define PI_F       3.141592653589793f
#define PI_12_F    1.5707963267948966f
#define PI_34_F    2.356194490192345f
#define PI_14_F    0.7853981633974483f
#define INV2PI_F   0.15915494309189535f

#define D3_5_F     0.061086523819801536f
#define D8_13_F    0.14189526818745917f
#define D26_565_F  0.46364671567952505f
#define D16_26_F   0.28379053637491834f
#define D36_87_F   0.64350289521467380f

#define SIN_F1_F   0.27999656988459544f
#define COS_F1_F   0.96000100046478220f
#define SIN_F2_F   0.60000142963530880f
#define COS_F2_F   0.79999892777837827f
#define SIN_U_F    0.12403445401859652f
#define COS_U_F    0.99227790841661646f

__device__ float        g_partials[4096];
__device__ unsigned int g_ticket;

// sin(C(theta)), C = reference's discretely-applied CORDIC rotation.
__device__ __forceinline__ float est_sin(float theta) {
    float fn = rintf(theta * INV2PI_F);
    float t  = fmaf(-fn, TWO_PI_F, theta);

    float at  = fabsf(t);
    bool  q2  = at > PI_34_F;
    bool  q1  = at > PI_14_F;
    float rot = q2 ? PI_F : (q1 ? PI_12_F : 0.0f);
    float r   = t - copysignf(rot, t);

    float ar    = fabsf(r);
    bool  f2    = ar >= D26_565_F;
    bool  f1    = ar >= D8_13_F;
    float Fv    = f2 ? D36_87_F : (f1 ? D16_26_F : 0.0f);
    float sinFs = copysignf(f2 ? SIN_F2_F : (f1 ? SIN_F1_F : 0.0f), r);
    float cosF  = f2 ? COS_F2_F : (f1 ? COS_F1_F : 1.0f);
    float r2    = r - copysignf(Fv, r);

    bool  um   = fabsf(r2) >= D3_5_F;
    float sinU = um ? copysignf(SIN_U_F, r2) : 0.0f;
    float cosU = um ? COS_U_F                : 1.0f;

    float sc = fmaf(sinFs, cosU,  cosF * sinU);
    float cc = fmaf(cosF,  cosU, -sinFs * sinU);

    float sgnt = copysignf(1.0f, t);
    return q2 ? -sc : (q1 ? sgnt * cc : sc);
}

__global__ void __launch_bounds__(256, 4) rope_dot_kernel(
    const float4* __restrict__ vec4,
    const float4* __restrict__ th4,
    const int*    __restrict__ m_ptr,
    float*        __restrict__ out,
    int n4)
{
    const float m = (float)(*m_ptr);
    const int stride  = gridDim.x * blockDim.x;     // 2^17
    const int stride2 = 2 * stride;                 // per-iteration advance
    const int iters   = n4 / stride2;               // 16 (exact)
    float acc0 = 0.0f, acc1 = 0.0f, acc2 = 0.0f, acc3 = 0.0f;

    int i = blockIdx.x * blockDim.x + threadIdx.x;

    // prologue: fill buffer (4 LDG.128 in flight)
    float4 va = __ldg(&vec4[i]);
    float4 ta = __ldg(&th4[i]);
    float4 vb = __ldg(&vec4[i + stride]);
    float4 tb = __ldg(&th4[i + stride]);

    for (int it = 1; it < iters; ++it) {
        int j = i + stride2;
        // next tile: 4 unconditional LDG.128 (2 KB/warp in flight)
        float4 van = __ldg(&vec4[j]);
        float4 tan_ = __ldg(&th4[j]);
        float4 vbn = __ldg(&vec4[j + stride]);
        float4 tbn = __ldg(&th4[j + stride]);
        // compute current tile: 4 independent est chains
        acc0 = fmaf(est_sin(m * ta.x), va.x, acc0);
        acc1 = fmaf(est_sin(m * ta.z), va.z, acc1);
        acc2 = fmaf(est_sin(m * tb.x), vb.x, acc2);
        acc3 = fmaf(est_sin(m * tb.z), vb.z, acc3);
        va = van; ta = tan_; vb = vbn; tb = tbn; i = j;
    }
    acc0 = fmaf(est_sin(m * ta.x), va.x, acc0);
    acc1 = fmaf(est_sin(m * ta.z), va.z, acc1);
    acc2 = fmaf(est_sin(m * tb.x), vb.x, acc2);
    acc3 = fmaf(est_sin(m * tb.z), vb.z, acc3);

    // generic tail (empty for this shape; keeps kernel shape-robust)
    for (int j = i + stride2; j < n4; j += stride) {
        float4 vt = __ldg(&vec4[j]);
        float4 tt = __ldg(&th4[j]);
        acc0 = fmaf(est_sin(m * tt.x), vt.x, acc0);
        acc1 = fmaf(est_sin(m * tt.z), vt.z, acc1);
    }
    float acc = (acc0 + acc1) + (acc2 + acc3);

    #pragma unroll
    for (int off = 16; off > 0; off >>= 1)
        acc += __shfl_down_sync(0xffffffffu, acc, off);

    __shared__ float sh[8];
    __shared__ bool  is_last;
    int lane = threadIdx.x & 31;
    int w    = threadIdx.x >> 5;
    if (lane == 0) sh[w] = acc;
    __syncthreads();
    if (threadIdx.x == 0) {
        float b = sh[0];
        #pragma unroll
        for (int k = 1; k < 8; k++) b += sh[k];
        g_partials[blockIdx.x] = b;
        __threadfence();
        unsigned tk = atomicAdd(&g_ticket, 1u);
        is_last = (tk == gridDim.x - 1);
    }
    __syncthreads();

    if (is_last) {
        double a = 0.0;
        for (int k = threadIdx.x; k < gridDim.x; k += blockDim.x)
            a += (double)g_partials[k];
        #pragma unroll
        for (int off = 16; off > 0; off >>= 1)
            a += __shfl_down_sync(0xffffffffu, a, off);
        __shared__ double shd[8];
        if (lane == 0) shd[w] = a;
        __syncthreads();
        if (threadIdx.x == 0) {
            double tot = shd[0];
            #pragma unroll
            for (int k = 1; k < 8; k++) tot += shd[k];
            out[0] = (float)(tot * (2.0 * (double)1.57f));
            g_ticket = 0;   // reset for next graph replay
        }
    }
}

extern "C" void kernel_launch(void* const* d_in, const int* in_sizes, int n_in,
                              void* d_out, int out_size) {
    const float4* vec4 = (const float4*)d_in[0];
    const float4* th4  = (const float4*)d_in[1];
    const int*    mptr = (const int*)d_in[2];

    int n  = in_sizes[0];
    int n4 = n / 4;

    const int threads = 256;
    const int blocks  = 512;   // 2^17 threads: n4/(2*2^17) = 16 exact iters

    rope_dot_kernel<<<blocks, threads>>>(vec4, th4, mptr, (float*)d_out, n4);
}

// round 11
// speedup vs baseline: 1.0743x; 1.0743x over previous
#include <cuda_runtime.h>
#include <math.h>

// ---------------------------------------------------------------------------
// ROPE_64252710748794: out = 2 * 1.57 * sum_k sin(C(theta_k)) * vec[2k]
// (theta pairs bitwise equal => pair collapse; see earlier rounds).
// est entirely in registers. Rounds 5-10 established: DRAM% pinned ~62-66%
// across occupancy 41-92%, -35% instructions, 1-2 KB/warp MLP => the binder
// is the memory path itself, not the SM. Round 11: evict-first streaming
// loads (__ldcs) — both streams are read-once, so default evict-normal L2
// policy is pure thrash. Config = round 9 (best: 1024 blks, 7 CTAs/SM,
// exact 16 iters, reg double-buffer) + unroll 2.
// ---------------------------------------------------------------------------

#define TWO_PI_F   6.283185307179586f
#define PI_F       3.141592653589793f
#define PI_12_F    1.5707963267948966f
#define PI_34_F    2.356194490192345f
#define PI_14_F    0.7853981633974483f
#define INV2PI_F   0.15915494309189535f

#define D3_5_F     0.061086523819801536f
#define D8_13_F    0.14189526818745917f
#define D26_565_F  0.46364671567952505f
#define D16_26_F   0.28379053637491834f
#define D36_87_F   0.64350289521467380f

#define SIN_F1_F   0.27999656988459544f
#define COS_F1_F   0.96000100046478220f
#define SIN_F2_F   0.60000142963530880f
#define COS_F2_F   0.79999892777837827f
#define SIN_U_F    0.12403445401859652f
#define COS_U_F    0.99227790841661646f

__device__ float        g_partials[4096];
__device__ unsigned int g_ticket;

// sin(C(theta)), C = reference's discretely-applied CORDIC rotation.
__device__ __forceinline__ float est_sin(float theta) {
    float fn = rintf(theta * INV2PI_F);
    float t  = fmaf(-fn, TWO_PI_F, theta);

    float at  = fabsf(t);
    bool  q2  = at > PI_34_F;
    bool  q1  = at > PI_14_F;
    float rot = q2 ? PI_F : (q1 ? PI_12_F : 0.0f);
    float r   = t - copysignf(rot, t);

    float ar    = fabsf(r);
    bool  f2    = ar >= D26_565_F;
    bool  f1    = ar >= D8_13_F;
    float Fv    = f2 ? D36_87_F : (f1 ? D16_26_F : 0.0f);
    float sinFs = copysignf(f2 ? SIN_F2_F : (f1 ? SIN_F1_F : 0.0f), r);
    float cosF  = f2 ? COS_F2_F : (f1 ? COS_F1_F : 1.0f);
    float r2    = r - copysignf(Fv, r);

    bool  um   = fabsf(r2) >= D3_5_F;
    float sinU = um ? copysignf(SIN_U_F, r2) : 0.0f;
    float cosU = um ? COS_U_F                : 1.0f;

    float sc = fmaf(sinFs, cosU,  cosF * sinU);
    float cc = fmaf(cosF,  cosU, -sinFs * sinU);

    float sgnt = copysignf(1.0f, t);
    return q2 ? -sc : (q1 ? sgnt * cc : sc);
}

__global__ void __launch_bounds__(256, 7) rope_dot_kernel(
    const float4* __restrict__ vec4,
    const float4* __restrict__ th4,
    const int*    __restrict__ m_ptr,
    float*        __restrict__ out,
    int n4)
{
    const float m = (float)(*m_ptr);
    const int stride = gridDim.x * blockDim.x;   // 2^18: divides n4 = 2^22
    const int iters  = n4 / stride;              // 16
    float acc0 = 0.0f, acc1 = 0.0f;

    int i = blockIdx.x * blockDim.x + threadIdx.x;
    float4 v = __ldcs(&vec4[i]);                 // evict-first: read-once data
    float4 t = __ldcs(&th4[i]);

    // steady state: unconditional next-tile loads, double-buffered
    #pragma unroll 2
    for (int it = 1; it < iters; ++it) {
        int j = i + stride;
        float4 vn = __ldcs(&vec4[j]);
        float4 tn = __ldcs(&th4[j]);
        acc0 = fmaf(est_sin(m * t.x), v.x, acc0);
        acc1 = fmaf(est_sin(m * t.z), v.z, acc1);
        v = vn; t = tn; i = j;
    }
    acc0 = fmaf(est_sin(m * t.x), v.x, acc0);
    acc1 = fmaf(est_sin(m * t.z), v.z, acc1);

    // generic tail (empty for this shape; keeps kernel shape-robust)
    for (int j = i + stride; j < n4; j += stride) {
        float4 vt = __ldcs(&vec4[j]);
        float4 tt = __ldcs(&th4[j]);
        acc0 = fmaf(est_sin(m * tt.x), vt.x, acc0);
        acc1 = fmaf(est_sin(m * tt.z), vt.z, acc1);
    }
    float acc = acc0 + acc1;

    #pragma unroll
    for (int off = 16; off > 0; off >>= 1)
        acc += __shfl_down_sync(0xffffffffu, acc, off);

    __shared__ float sh[8];
    __shared__ bool  is_last;
    int lane = threadIdx.x & 31;
    int w    = threadIdx.x >> 5;
    if (lane == 0) sh[w] = acc;
    __syncthreads();
    if (threadIdx.x == 0) {
        float b = sh[0];
        #pragma unroll
        for (int k = 1; k < 8; k++) b += sh[k];
        g_partials[blockIdx.x] = b;
        __threadfence();
        unsigned tk = atomicAdd(&g_ticket, 1u);
        is_last = (tk == gridDim.x - 1);
    }
    __syncthreads();

    if (is_last) {
        double a = 0.0;
        for (int k = threadIdx.x; k < gridDim.x; k += blockDim.x)
            a += (double)g_partials[k];
        #pragma unroll
        for (int off = 16; off > 0; off >>= 1)
            a += __shfl_down_sync(0xffffffffu, a, off);
        __shared__ double shd[8];
        if (lane == 0) shd[w] = a;
        __syncthreads();
        if (threadIdx.x == 0) {
            double tot = shd[0];
            #pragma unroll
            for (int k = 1; k < 8; k++) tot += shd[k];
            out[0] = (float)(tot * (2.0 * (double)1.57f));
            g_ticket = 0;   // reset for next graph replay
        }
    }
}

extern "C" void kernel_launch(void* const* d_in, const int* in_sizes, int n_in,
                              void* d_out, int out_size) {
    const float4* vec4 = (const float4*)d_in[0];
    const float4* th4  = (const float4*)d_in[1];
    const int*    mptr = (const int*)d_in[2];

    int n  = in_sizes[0];
    int n4 = n / 4;

    const int threads = 256;
    const int blocks  = 1024;  // 2^18 threads: n4/threads = 16 exact iters

    rope_dot_kernel<<<blocks, threads>>>(vec4, th4, mptr, (float*)d_out, n4);
}